// round 17
// baseline (speedup 1.0000x reference)
#include <cuda_runtime.h>
#include <cuda_fp16.h>
#include <math.h>
#include <stdint.h>

// Problem constants (fixed by setup_inputs)
#define B_   64
#define L_   680
#define C_   1024
#define NSEG 10

__constant__ int       c_start[NSEG] = {0,1,5,14,30,55,91,155,255,424};
__constant__ int       c_len[NSEG]   = {1,4,9,16,25,36,64,100,169,256};
__constant__ long long c_base[NSEG]  = {0LL,8192LL,73728LL,294912LL,819200LL,
                                        1843200LL,3612672LL,7282688LL,13836288LL,26296320LL};
// Tile prefix tables for BM=256 tiles:
//   mtiles_i = ceil(64*len_i/256) = {1,1,3,4,7,9,16,25,43,64}
__constant__ int c_stp[NSEG + 1] = {0,1,3,12,28,63,117,229,429,816,1456};
__constant__ int c_atp[NSEG + 1] = {0,8,16,40,72,128,200,328,528,872,1384};

// Static device scratch
__device__ __align__(16) __half g_xh  [44564480]; // x as half
__device__ __align__(16) __half g_memh[1310720];  // mem as half
__device__ __align__(16) __half g_Q   [44564480]; // Q (half)
__device__ __align__(16) __half g_Kh  [1310720];  // [1280][1024] K (half)
__device__ __align__(16) __half g_Vt  [1310720];  // [1024][1280] V^T (half)
__device__ __align__(16) float  g_S   [47267840]; // scores (f32, segment-packed)
__device__ __align__(16) __half g_P   [47267840]; // attn probs (half, same packing)
__device__ __align__(16) __half g_MC  [44564480]; // mem_combined (half)
__device__ __align__(16) __half g_mid [5570560];  // [43520][128] (half)
__device__ __align__(16) __half g_WqT [1048576];  // Wq^T [1024][1024]
__device__ __align__(16) __half g_wkvT[2097152];  // [2048][1024] Wk^T|Wv^T
__device__ __align__(16) __half g_w12T[131072];   // [128][1024] wk1^T|wv1^T
__device__ __align__(16) __half g_w34T[131072];   // wk2^T [1024][64] @0 | wv2^T @65536
__device__ float  g_b12 [128];                    // bk1|bv1 (f32)

// Smem: per stage, A 256 rows x 144B = 36864, B 128 rows x 144B = 18432
#define ROW_BYTES    144
#define A_STAGE_B    36864
#define B_STAGE_B    18432
#define STAGE_B      55296
#define NSTAGE       3
#define SMEM_BYTES   (NSTAGE * STAGE_B)   // 165888

#define NTHREADS     512

__device__ __forceinline__ void cp16(uint32_t dst, const void* src, int szbytes) {
    asm volatile("cp.async.cg.shared.global [%0], [%1], 16, %2;"
                 :: "r"(dst), "l"(src), "r"(szbytes));
}
__device__ __forceinline__ void cp_commit() { asm volatile("cp.async.commit_group;"); }
__device__ __forceinline__ void cp_wait1()  { asm volatile("cp.async.wait_group 1;"); }
__device__ __forceinline__ void cp_wait0()  { asm volatile("cp.async.wait_group 0;"); }

// ---------------------------------------------------------------------------
// FP16 NT GEMM core: one 256x128 C-tile at (m0, n0). 512 threads, 16 warps,
// warp tile 32x64 (wm=(w&7)*32, wn=(w>>3)*64) -> acc 64 regs/thread so the
// whole CTA fits the register file at 16 warps/SM (2x the R16 warp count,
// same smem), hiding LDS->HMMA latency.
//   A: [M,K] half (lda); alen>0 => row remap (m/alen)*680+astart+(m%alen)
//   B: [N,K] half (ldb); n0+128 <= N (all N multiples of 128)
//   C: [M,N]; clen>0 => row remap; half or f32 output
// K % 64 == 0. M edge zero-filled + store-guarded.
// Loaders: threads 0-255 stage A (8 cp16), threads 256-511 stage B (4 cp16).
// 3-stage cp.async ring, one __syncthreads per K-chunk, scalar fragment LDS.
// ---------------------------------------------------------------------------
__device__ __forceinline__ void hcore(
    const __half* __restrict__ A, int lda,
    const __half* __restrict__ B, int ldb,
    void* __restrict__ C, int ldc,
    int M, int K,
    int alen, int astart, int clen, int cstart,
    const float* __restrict__ bias,
    const float* __restrict__ gate_logit,
    int m0, int n0, bool outHalf)
{
    extern __shared__ char smraw[];
    const uint32_t smb = (uint32_t)__cvta_generic_to_shared(smraw);

    const int tid  = threadIdx.x;
    const int lane = tid & 31;
    const int w    = tid >> 5;        // 0..15
    const int wm   = (w & 7) * 32;    // 8 m-warps
    const int wn   = (w >> 3) * 64;   // 2 n-warps
    const int g    = lane >> 2;
    const int t4   = lane & 3;

    float acc[2][8][4];
    #pragma unroll
    for (int i = 0; i < 2; i++)
        #pragma unroll
        for (int j = 0; j < 8; j++)
            #pragma unroll
            for (int k = 0; k < 4; k++) acc[i][j][k] = 0.f;

    // ---- A loader (threads 0-255): row m0+tid, 64 halves/chunk = 8 cp16 ----
    const bool isA  = tid < 256;
    const int am    = m0 + tid;                 // valid when isA
    const bool amOK = isA && (am < M);
    const int amc   = amOK ? am : 0;
    long long arow = (alen > 0)
        ? (long long)(amc / alen) * L_ + astart + (amc % alen)
        : (long long)amc;
    const __half* Aptr = A + arow * (long long)lda;
    const int a_sz = amOK ? 16 : 0;
    const uint32_t a_dst = smb + (uint32_t)(tid & 255) * ROW_BYTES;

    // ---- B loader (threads 256-511): row (tid-256)>>1, half-row (tid&1) ----
    const int bt   = tid - 256;                 // valid when !isA
    const int brow = (bt < 0 ? 0 : bt) >> 1;
    const int bp   = bt & 1;
    const __half* Bptr = B + (long long)(n0 + brow) * ldb + bp * 32;
    const uint32_t b_dst = smb + A_STAGE_B + (uint32_t)brow * ROW_BYTES + (uint32_t)bp * 64u;

    auto issue = [&](int s, int chunk) {
        int k0 = chunk * 64;
        uint32_t soff = (uint32_t)s * STAGE_B;
        if (isA) {
            const __half* ap = Aptr + k0;
            uint32_t ad = a_dst + soff;
            #pragma unroll
            for (int j = 0; j < 8; j++)
                cp16(ad + j * 16, ap + j * 8, a_sz);
        } else {
            const __half* bpp = Bptr + k0;
            uint32_t bd = b_dst + soff;
            #pragma unroll
            for (int j = 0; j < 4; j++)
                cp16(bd + j * 16, bpp + j * 8, 16);
        }
        cp_commit();
    };

    auto compute = [&](int s) {
        const char* As = smraw + s * STAGE_B;
        const char* Bs = smraw + s * STAGE_B + A_STAGE_B;
        #pragma unroll
        for (int kb = 0; kb < 4; kb++) {
            const int kB = kb * 32;     // 16 halves = 32 bytes per k-step
            uint32_t af[2][4], bf[8][2];
            #pragma unroll
            for (int mi = 0; mi < 2; mi++) {
                int base = (wm + mi * 16 + g) * ROW_BYTES + kB + t4 * 4;
                af[mi][0] = *(const uint32_t*)(As + base);
                af[mi][1] = *(const uint32_t*)(As + base + 8 * ROW_BYTES);
                af[mi][2] = *(const uint32_t*)(As + base + 16);
                af[mi][3] = *(const uint32_t*)(As + base + 8 * ROW_BYTES + 16);
            }
            #pragma unroll
            for (int ni = 0; ni < 8; ni++) {
                int bb = (wn + ni * 8 + g) * ROW_BYTES + kB + t4 * 4;
                bf[ni][0] = *(const uint32_t*)(Bs + bb);
                bf[ni][1] = *(const uint32_t*)(Bs + bb + 16);
            }
            #pragma unroll
            for (int mi = 0; mi < 2; mi++)
                #pragma unroll
                for (int ni = 0; ni < 8; ni++) {
                    asm volatile(
                        "mma.sync.aligned.m16n8k16.row.col.f32.f16.f16.f32 "
                        "{%0,%1,%2,%3},{%4,%5,%6,%7},{%8,%9},{%0,%1,%2,%3};"
                        : "+f"(acc[mi][ni][0]), "+f"(acc[mi][ni][1]),
                          "+f"(acc[mi][ni][2]), "+f"(acc[mi][ni][3])
                        : "r"(af[mi][0]), "r"(af[mi][1]),
                          "r"(af[mi][2]), "r"(af[mi][3]),
                          "r"(bf[ni][0]), "r"(bf[ni][1]));
                }
        }
    };

    // ---- 3-stage ring, single sync per chunk ----
    const int T = K >> 6;
    issue(0, 0);
    if (T > 1) issue(1, 1);
    for (int i = 0; i < T; i++) {
        if (i + 2 < T) cp_wait1(); else cp_wait0();
        __syncthreads();
        if (i + 2 < T) issue((i + 2) % NSTAGE, i + 2);
        compute(i % NSTAGE);
    }

    // ---- epilogue ----
    float gate = 1.0f;
    if (gate_logit) gate = 1.0f / (1.0f + expf(-(*gate_logit)));

    #pragma unroll
    for (int mi = 0; mi < 2; mi++) {
        #pragma unroll
        for (int rr = 0; rr < 2; rr++) {
            int m = m0 + wm + mi * 16 + g + rr * 8;
            if (m >= M) continue;
            long long crow = (clen > 0)
                ? (long long)(m / clen) * L_ + cstart + (m % clen)
                : (long long)m;
            #pragma unroll
            for (int ni = 0; ni < 8; ni++) {
                int n = n0 + wn + ni * 8 + t4 * 2;
                float v0 = acc[mi][ni][rr * 2 + 0];
                float v1 = acc[mi][ni][rr * 2 + 1];
                if (bias) { v0 += bias[n]; v1 += bias[n + 1]; }
                v0 *= gate; v1 *= gate;
                if (outHalf) {
                    __half* cp = (__half*)C + crow * (long long)ldc + n;
                    *(__half2*)cp = __floats2half2_rn(v0, v1);
                } else {
                    float* cp = (float*)C + crow * (long long)ldc + n;
                    cp[0] = v0; cp[1] = v1;
                }
            }
        }
    }
}

// ---------------------------------------------------------------------------
__global__ __launch_bounds__(NTHREADS)
void hgemm(const __half* __restrict__ A, int lda,
           const __half* __restrict__ B, int ldb,
           void* __restrict__ C, int ldc,
           int M, int K,
           const float* __restrict__ bias,
           const float* __restrict__ gate_logit,
           int outHalf)
{
    hcore(A, lda, B, ldb, C, ldc, M, K, 0, 0, 0, 0,
          bias, gate_logit,
          blockIdx.y * 256, blockIdx.x * 128, outHalf != 0);
}

// Fused projections:
//   tiles 0..1359:    Q  = x @ Wq            (170 m x 8 n)
//   tiles 1360..1399: K  = mem @ Wk          (5 m x 8 n)
//   tiles 1400..1439: Vt = Wv^T "@" mem^T    (A=WvT, B=memh; 4 m x 10 n)
__global__ __launch_bounds__(NTHREADS)
void proj_kernel()
{
    int t = blockIdx.x;
    if (t < 1360) {
        int tm = t >> 3, tn = t & 7;
        hcore(g_xh, C_, g_WqT, C_, g_Q, C_, B_ * L_, C_,
              0, 0, 0, 0, nullptr, nullptr, tm * 256, tn * 128, true);
    } else if (t < 1400) {
        int local = t - 1360;
        int tm = local >> 3, tn = local & 7;
        hcore(g_memh, C_, g_wkvT, C_, g_Kh, C_, NSEG * 128, C_,
              0, 0, 0, 0, nullptr, nullptr, tm * 256, tn * 128, true);
    } else {
        int local = t - 1400;
        int tm = local / 10, tn = local % 10;
        hcore(g_wkvT + 1048576, C_, g_memh, C_, g_Vt, 1280, 1024, C_,
              0, 0, 0, 0, nullptr, nullptr, tm * 256, tn * 128, true);
    }
}

// Fused scores: all 10 segments (1456 tiles). A=Q remapped; C = f32 scores.
__global__ __launch_bounds__(NTHREADS)
void scores_kernel()
{
    int t = blockIdx.x;
    int seg = 0;
    #pragma unroll
    for (int i = 1; i < NSEG; i++) if (t >= c_stp[i]) seg = i;
    int local = t - c_stp[seg];
    int nt = seg + 1;
    int tm = local / nt;
    int tn = local - tm * nt;
    int len = c_len[seg], start = c_start[seg];
    int Nseg = 128 * nt, Mseg = 64 * len;
    hcore(g_Q, C_, g_Kh, C_, g_S + c_base[seg], Nseg,
          Mseg, C_, len, start, 0, 0, nullptr, nullptr,
          tm * 256, tn * 128, false);
}

// Fused attn@V: all 10 segments (1384 tiles). A = probs (half); C = MC (half).
__global__ __launch_bounds__(NTHREADS)
void attnv_kernel()
{
    int t = blockIdx.x;
    int seg = 0;
    #pragma unroll
    for (int i = 1; i < NSEG; i++) if (t >= c_atp[i]) seg = i;
    int local = t - c_atp[seg];
    int tm = local >> 3;
    int tn = local & 7;
    int len = c_len[seg], start = c_start[seg];
    int Nseg = 128 * (seg + 1), Mseg = 64 * len;
    hcore(g_P + c_base[seg], Nseg, g_Vt, 1280, g_MC, C_,
          Mseg, Nseg, 0, 0, len, start, nullptr, nullptr,
          tm * 256, tn * 128, true);
}

// ---------------------------------------------------------------------------
// Row softmax: single gmem read (smem row buffer), single exp, half write.
// scale = (1/32)/clip(exp(log_temp), 0.05, 1)
// ---------------------------------------------------------------------------
__global__ void softmax_kernel(const float* __restrict__ log_temp)
{
    __shared__ float buf[1280];
    __shared__ float sh[8];

    int row = blockIdx.x;
    int b = row / L_;
    int l = row - b * L_;

    int seg = 0;
    #pragma unroll
    for (int s2 = 1; s2 < NSEG; s2++)
        if (l >= c_start[s2]) seg = s2;

    const int n   = 128 * (seg + 1);
    const int len = c_len[seg];
    long long off = c_base[seg] + ((long long)b * len + (l - c_start[seg])) * (long long)n;
    const float* p = g_S + off;
    __half* q = g_P + off;

    float t = expf(*log_temp);
    t = fminf(fmaxf(t, 0.05f), 1.0f);
    const float scale = (1.0f / 32.0f) / t;

    const int lane = threadIdx.x & 31;
    const int w    = threadIdx.x >> 5;

    float m = -1e30f;
    for (int j = threadIdx.x; j < n; j += 256) {
        float v = p[j] * scale;
        buf[j] = v;
        m = fmaxf(m, v);
    }
    #pragma unroll
    for (int o = 16; o; o >>= 1) m = fmaxf(m, __shfl_xor_sync(0xffffffffu, m, o));
    if (lane == 0) sh[w] = m;
    __syncthreads();
    m = sh[lane & 7];
    #pragma unroll
    for (int o = 4; o; o >>= 1) m = fmaxf(m, __shfl_xor_sync(0xffffffffu, m, o));

    float sum = 0.f;
    for (int j = threadIdx.x; j < n; j += 256) {
        float e = expf(buf[j] - m);
        buf[j] = e;
        sum += e;
    }
    #pragma unroll
    for (int o = 16; o; o >>= 1) sum += __shfl_xor_sync(0xffffffffu, sum, o);
    __syncthreads();
    if (lane == 0) sh[w] = sum;
    __syncthreads();
    sum = sh[lane & 7];
    #pragma unroll
    for (int o = 4; o; o >>= 1) sum += __shfl_xor_sync(0xffffffffu, sum, o);

    const float inv = 1.0f / sum;
    for (int j = threadIdx.x; j < n; j += 256)
        q[j] = __float2half_rn(buf[j] * inv);
}

// ---------------------------------------------------------------------------
// Fused prologue: f2h of x and mem in one launch
// ---------------------------------------------------------------------------
__global__ void f2h_all(const float* __restrict__ x, const float* __restrict__ mem)
{
    int bid = blockIdx.x;
    if (bid < 43520) {
        int i = bid * 256 + threadIdx.x;
        float4 v = ((const float4*)x)[i];
        ((__half2*)g_xh)[i * 2 + 0] = __floats2half2_rn(v.x, v.y);
        ((__half2*)g_xh)[i * 2 + 1] = __floats2half2_rn(v.z, v.w);
    } else {
        int i = (bid - 43520) * 256 + threadIdx.x;
        float4 v = ((const float4*)mem)[i];
        ((__half2*)g_memh)[i * 2 + 0] = __floats2half2_rn(v.x, v.y);
        ((__half2*)g_memh)[i * 2 + 1] = __floats2half2_rn(v.z, v.w);
    }
}

// Fused weight pack: all 7 transposes + bias pack in one launch (3329 blocks).
__global__ void pack_weights(const float* __restrict__ Wq,
                             const float* __restrict__ Wk,
                             const float* __restrict__ Wv,
                             const float* __restrict__ wk1,
                             const float* __restrict__ wv1,
                             const float* __restrict__ wk2,
                             const float* __restrict__ wv2,
                             const float* __restrict__ bk1,
                             const float* __restrict__ bv1)
{
    int bid = blockIdx.x;
    if (bid == 3328) {
        int i = threadIdx.x;
        if (i < 64) { g_b12[i] = bk1[i]; g_b12[64 + i] = bv1[i]; }
        return;
    }
    const float* src; __half* dst;
    int sld, dld, R, Cc, base;
    if      (bid < 1024) { src = Wq;  dst = g_WqT;            sld = 1024; dld = 1024; R = 1024; Cc = 1024; base = 0; }
    else if (bid < 2048) { src = Wk;  dst = g_wkvT;           sld = 1024; dld = 1024; R = 1024; Cc = 1024; base = 1024; }
    else if (bid < 3072) { src = Wv;  dst = g_wkvT + 1048576; sld = 1024; dld = 1024; R = 1024; Cc = 1024; base = 2048; }
    else if (bid < 3136) { src = wk1; dst = g_w12T;           sld = 64;   dld = 1024; R = 1024; Cc = 64;   base = 3072; }
    else if (bid < 3200) { src = wv1; dst = g_w12T + 65536;   sld = 64;   dld = 1024; R = 1024; Cc = 64;   base = 3136; }
    else if (bid < 3264) { src = wk2; dst = g_w34T;           sld = 1024; dld = 64;   R = 64;   Cc = 1024; base = 3200; }
    else                 { src = wv2; dst = g_w34T + 65536;   sld = 1024; dld = 64;   R = 64;   Cc = 1024; base = 3264; }
    int local = bid - base;
    int tiles_x = (Cc + 31) >> 5;
    int tx = local % tiles_x, ty = local / tiles_x;

    __shared__ float tbuf[32][33];
    int thx = threadIdx.x & 31, thy = threadIdx.x >> 5;
    int xx = tx * 32 + thx, yy = ty * 32 + thy;
    if (xx < Cc && yy < R) tbuf[thy][thx] = src[(long long)yy * sld + xx];
    __syncthreads();
    int xo = ty * 32 + thx, yo = tx * 32 + thy;
    if (xo < R && yo < Cc)
        dst[(long long)yo * dld + xo] = __float2half_rn(tbuf[thx][thy]);
}

__global__ void tail_kernel(float* out, long long off)
{
    if (threadIdx.x < 2) out[off + threadIdx.x] = 0.f;
}

// ---------------------------------------------------------------------------
extern "C" void kernel_launch(void* const* d_in, const int* in_sizes, int n_in,
                              void* d_out, int out_size)
{
    const float* x   = (const float*)d_in[0];
    const float* mem = (const float*)d_in[1];
    const float* Wq  = (const float*)d_in[2];
    const float* Wk  = (const float*)d_in[3];
    const float* Wv  = (const float*)d_in[4];
    const float* wk1 = (const float*)d_in[5];
    const float* bk1 = (const float*)d_in[6];
    const float* wk2 = (const float*)d_in[7];
    const float* bk2 = (const float*)d_in[8];
    const float* wv1 = (const float*)d_in[9];
    const float* bv1 = (const float*)d_in[10];
    const float* wv2 = (const float*)d_in[11];
    const float* bv2 = (const float*)d_in[12];
    const float* gk  = (const float*)d_in[13];
    const float* gv  = (const float*)d_in[14];
    const float* lt  = (const float*)d_in[15];
    float* out = (float*)d_out;

    __half *MC, *mid, *w12T, *w34T;
    float *b12;
    cudaGetSymbolAddress((void**)&MC,   g_MC);
    cudaGetSymbolAddress((void**)&mid,  g_mid);
    cudaGetSymbolAddress((void**)&w12T, g_w12T);
    cudaGetSymbolAddress((void**)&w34T, g_w34T);
    cudaGetSymbolAddress((void**)&b12,  g_b12);

    cudaFuncSetAttribute(hgemm,         cudaFuncAttributeMaxDynamicSharedMemorySize, SMEM_BYTES);
    cudaFuncSetAttribute(proj_kernel,   cudaFuncAttributeMaxDynamicSharedMemorySize, SMEM_BYTES);
    cudaFuncSetAttribute(scores_kernel, cudaFuncAttributeMaxDynamicSharedMemorySize, SMEM_BYTES);
    cudaFuncSetAttribute(attnv_kernel,  cudaFuncAttributeMaxDynamicSharedMemorySize, SMEM_BYTES);

    // 0) fused prologue: converts + weight packs (2 launches)
    f2h_all<<<44800, 256>>>(x, mem);
    pack_weights<<<3329, 1024>>>(Wq, Wk, Wv, wk1, wv1, wk2, wv2, bk1, bv1);

    // 1) fused projections: Q, K, and V^T in one launch
    proj_kernel<<<1440, NTHREADS, SMEM_BYTES>>>();

    // 2) all score GEMMs (f32 scores)
    scores_kernel<<<1456, NTHREADS, SMEM_BYTES>>>();

    // 3) softmax: f32 scores -> half probs (single gmem pass)
    softmax_kernel<<<B_ * L_, 256>>>(lt);

    // 4) all attn @ V GEMMs (half MC)
    attnv_kernel<<<1384, NTHREADS, SMEM_BYTES>>>();

    // 5) mid = MC @ [wk1|wv1] + [bk1|bv1] (half out)
    hgemm<<<dim3(1, 170), NTHREADS, SMEM_BYTES>>>(MC, C_, w12T, C_, mid, 128,
                                                  B_ * L_, C_, b12, nullptr, 1);

    // 6) up-projections with bias+gate epilogue (f32 final outputs)
    hgemm<<<dim3(8, 170), NTHREADS, SMEM_BYTES>>>(mid,      128, w34T,         64,
                                                  out, C_, B_ * L_, 64, bk2, gk, 0);
    hgemm<<<dim3(8, 170), NTHREADS, SMEM_BYTES>>>(mid + 64, 128, w34T + 65536, 64,
                                                  out + (long long)B_ * L_ * C_, C_,
                                                  B_ * L_, 64, bv2, gv, 0);

    // 7) trailing two scalar zeros
    tail_kernel<<<1, 32>>>(out, 2LL * B_ * L_ * C_);
}